// round 8
// baseline (speedup 1.0000x reference)
#include <cuda_runtime.h>
#include <math.h>
#include <stdint.h>

// ============================================================================
// TemporalSamplingUpSampler — ONE fused kernel.
//
// Grid (T/1024, C/CPB). Every block:
//   1) block-parallel plan into smem (identical arithmetic to round-6):
//      softmax -> Lp, r = max(rint(Lp),0), prefix sum cum[], total, l_max;
//      then per-k  sc = lmax/Lp, tf = (lmax-Lp)/Lp  (weight hoisting).
//   2) per thread: 4 output columns -> slot (exact int mul/shift for pow2 T),
//      LDS binary search -> k, j -> weight w (one fdiv per column).
//   3) fill CPB c-rows: out[c,tt] = A[c,k]*w, broadcast A read fast path,
//      float4 evict-first stores.
//
// No intermediate arrays, no extra launches: kills the ~6us of expand +
// plan-roundtrip overhead on top of the 24.6us fill.
// ============================================================================

#define MAX_K 1024
#define CPB   16

__global__ void __launch_bounds__(256) fused_kernel(
    const float* __restrict__ L,
    const float* __restrict__ A,
    float* __restrict__ out,
    int K, int T, int C, float Tf)
{
    __shared__ float s_sc[MAX_K];       // lmax / Lp
    __shared__ float s_tf[MAX_K];       // (lmax - Lp) / Lp
    __shared__ float s_Lp[MAX_K];
    __shared__ int   s_cum[MAX_K + 1];
    __shared__ float sred[32];
    __shared__ int   sscan[32];
    __shared__ int   s_total;
    __shared__ float s_lmax;

    const int t    = threadIdx.x;
    const int lane = t & 31;
    const int warp = t >> 5;
    const int nw   = blockDim.x >> 5;                     // 8
    const int EPT  = (K + blockDim.x - 1) / blockDim.x;   // 1 for K=256
    const int base = t * EPT;

    // ---------------- plan (identical arithmetic to round-6) ----------------
    float lv[4];
#pragma unroll
    for (int i = 0; i < 4; i++) {
        int k = base + i;
        lv[i] = (i < EPT && k < K) ? __ldg(L + k) : -INFINITY;
    }

    // block max(L)
    float mx = fmaxf(fmaxf(lv[0], lv[1]), fmaxf(lv[2], lv[3]));
    for (int o = 16; o; o >>= 1) mx = fmaxf(mx, __shfl_xor_sync(0xffffffffu, mx, o));
    if (lane == 0) sred[warp] = mx;
    __syncthreads();
    if (warp == 0) {
        float v = (lane < nw) ? sred[lane] : -INFINITY;
        for (int o = 16; o; o >>= 1) v = fmaxf(v, __shfl_xor_sync(0xffffffffu, v, o));
        if (lane == 0) sred[0] = v;
    }
    __syncthreads();
    mx = sred[0];
    __syncthreads();

    // block sum(exp)
    float e[4];
    float s = 0.0f;
#pragma unroll
    for (int i = 0; i < 4; i++) {
        int k = base + i;
        e[i] = (i < EPT && k < K) ? expf(lv[i] - mx) : 0.0f;
        s += e[i];
    }
    for (int o = 16; o; o >>= 1) s += __shfl_xor_sync(0xffffffffu, s, o);
    if (lane == 0) sred[warp] = s;
    __syncthreads();
    if (warp == 0) {
        float v = (lane < nw) ? sred[lane] : 0.0f;
        for (int o = 16; o; o >>= 1) v += __shfl_xor_sync(0xffffffffu, v, o);
        if (lane == 0) sred[0] = v;
    }
    __syncthreads();
    const float sum = sred[0];
    __syncthreads();

    // Lp -> smem, r = max(rint(Lp),0), maxLp
    float maxLp = -INFINITY;
    int rr[4];
    int rs = 0;
#pragma unroll
    for (int i = 0; i < 4; i++) {
        int k = base + i;
        if (i < EPT && k < K) {
            float Lp = Tf * __fdiv_rn(e[i], sum);
            s_Lp[k] = Lp;
            maxLp = fmaxf(maxLp, Lp);
            int r = (int)rintf(Lp);        // half-to-even == np.rint
            if (r < 0) r = 0;
            rr[i] = r;
            rs += r;
        } else rr[i] = 0;
    }

    // block max(Lp)
    float mLp = maxLp;
    for (int o = 16; o; o >>= 1) mLp = fmaxf(mLp, __shfl_xor_sync(0xffffffffu, mLp, o));
    if (lane == 0) sred[warp] = mLp;
    __syncthreads();
    if (warp == 0) {
        float v = (lane < nw) ? sred[lane] : -INFINITY;
        for (int o = 16; o; o >>= 1) v = fmaxf(v, __shfl_xor_sync(0xffffffffu, v, o));
        if (lane == 0) sred[0] = v;
    }

    // block scan of rs (two-level shfl)
    int incl = rs;
    for (int o = 1; o < 32; o <<= 1) {
        int v = __shfl_up_sync(0xffffffffu, incl, o);
        if (lane >= o) incl += v;
    }
    if (lane == 31) sscan[warp] = incl;
    __syncthreads();
    if (warp == 0) {
        int v = (lane < nw) ? sscan[lane] : 0;
        for (int o = 1; o < 32; o <<= 1) {
            int u = __shfl_up_sync(0xffffffffu, v, o);
            if (lane >= o) v += u;
        }
        if (lane < nw) sscan[lane] = v;    // inclusive warp totals
    }
    __syncthreads();

    const int warp_excl = (warp == 0) ? 0 : sscan[warp - 1];
    int running = warp_excl + (incl - rs);     // exclusive prefix, this thread
#pragma unroll
    for (int i = 0; i < 4; i++) {
        int k = base + i;
        if (i < EPT && k < K) {
            running += rr[i];
            s_cum[k + 1] = running;
        }
    }
    if (t == 0) {
        s_cum[0] = 0;
        s_total  = sscan[nw - 1];
        double dm = (double)sred[0] + 0.5;
        s_lmax = (float)(long long)dm;     // int(max+0.5), trunc==floor (>=0)
    }
    __syncthreads();

    // per-k hoisted weight terms: sc = lmax/Lp, tf = (lmax-Lp)/Lp
    const float lmaxf = s_lmax;
#pragma unroll
    for (int i = 0; i < 4; i++) {
        int k = base + i;
        if (i < EPT && k < K) {
            const float Lp = s_Lp[k];
            s_sc[k] = __fdiv_rn(lmaxf, Lp);
            s_tf[k] = __fdiv_rn(__fadd_rn(lmaxf, -Lp), Lp);
        }
    }
    __syncthreads();

    // ---------------- (k, w) for this thread's 4 columns ----------------
    const int tt0 = (blockIdx.x * blockDim.x + threadIdx.x) * 4;
    if (tt0 >= T) return;

    const int   total = s_total;
    const bool  pow2  = (T & (T - 1)) == 0;
    const int   shift = __ffs(T) - 1;
    const double ratio = (double)total / (double)T;

    float4 w;
    int4   kk;
    float* wv = &w.x;
    int*   kv = &kk.x;

#pragma unroll
    for (int i = 0; i < 4; i++) {
        int tt = tt0 + i;
        if (tt > T - 1) tt = T - 1;

        long long slot;
        if (pow2) {
            slot = ((long long)tt * (long long)total) >> shift;  // exact
        } else {
            slot = (long long)floor((double)tt * ratio);
        }
        if (slot > (long long)(total - 1)) slot = total - 1;
        if (slot < 0) slot = 0;

        int lo = 0, hi = K;
        const int si = (int)slot;
        while (hi - lo > 1) {
            int mid = (lo + hi) >> 1;
            if (s_cum[mid] <= si) lo = mid; else hi = mid;
        }
        const int k = lo;
        const int j = si - s_cum[k];

        const float x  = __fadd_rn(__fdiv_rn(__fadd_rn(__fmul_rn(2.0f, (float)j), 1.0f), lmaxf), -1.0f);
        const float xs = __fadd_rn(__fmul_rn(s_sc[k], x), s_tf[k]);
        const float p  = __fmul_rn(__fadd_rn(__fmul_rn(__fadd_rn(xs, 1.0f), 100.0f), -1.0f), 0.5f);
        const float p0 = floorf(p);
        const float w1 = __fadd_rn(p, -p0);
        const float in0 = (p0 >=  0.0f && p0 <= 99.0f) ? 1.0f : 0.0f;
        const float in1 = (p0 >= -1.0f && p0 <= 98.0f) ? 1.0f : 0.0f;
        wv[i] = __fadd_rn(__fmul_rn(__fadd_rn(1.0f, -w1), in0), __fmul_rn(w1, in1));
        kv[i] = k;
    }

    // ---------------- fill CPB c-rows ----------------
    const int c0 = blockIdx.y * CPB;
    int c1 = c0 + CPB;
    if (c1 > C) c1 = C;

    const bool vec  = (tt0 + 3 < T);
    const bool same = (kk.x == kk.w);   // k monotone: ends equal => all equal

    if (same & vec) {
        const float* Ap = A + (size_t)c0 * (size_t)K + kk.x;
        float* op = out + (size_t)c0 * (size_t)T + tt0;
#pragma unroll 4
        for (int c = c0; c < c1; ++c) {
            const float a = __ldg(Ap);
            float4 o = make_float4(a * w.x, a * w.y, a * w.z, a * w.w);
            __stcs(reinterpret_cast<float4*>(op), o);
            Ap += K;
            op += T;
        }
    } else {
        for (int c = c0; c < c1; ++c) {
            const float* Ar = A + (size_t)c * (size_t)K;
            float4 o;
            o.x = __ldg(Ar + kk.x) * w.x;
            o.y = __ldg(Ar + kk.y) * w.y;
            o.z = __ldg(Ar + kk.z) * w.z;
            o.w = __ldg(Ar + kk.w) * w.w;
            float* op = out + (size_t)c * (size_t)T + tt0;
            if (vec) {
                __stcs(reinterpret_cast<float4*>(op), o);
            } else {
                if (tt0     < T) op[0] = o.x;
                if (tt0 + 1 < T) op[1] = o.y;
                if (tt0 + 2 < T) op[2] = o.z;
                if (tt0 + 3 < T) op[3] = o.w;
            }
        }
    }
}

// ---------------------------------------------------------------------------
extern "C" void kernel_launch(void* const* d_in, const int* in_sizes, int n_in,
                              void* d_out, int out_size)
{
    const float* A = (const float*)d_in[0];   // [C, K]
    const float* L = (const float*)d_in[1];   // [K]

    const int K = in_sizes[1];
    const int C = in_sizes[0] / K;
    const int T = out_size / C;               // out is [1, C, T]

    const int cols_per_block = 256 * 4;
    const int gx = (T + cols_per_block - 1) / cols_per_block;

    dim3 grid(gx, (C + CPB - 1) / CPB);
    fused_kernel<<<grid, 256>>>(L, A, (float*)d_out, K, T, C, (float)T);
}

// round 9
// speedup vs baseline: 1.2412x; 1.2412x over previous
#include <cuda_runtime.h>
#include <math.h>
#include <stdint.h>

// ============================================================================
// TemporalSamplingUpSampler — 2-phase (round-6 structure, new fill):
//   1) expand_kernel<<<128,256>>>: per-block fused plan (softmax, rint,
//      prefix-sum, lmax) + column expansion -> d_w[T], d_k[T].
//   2) fill_kernel<<<(64,16),256>>>: 8 cols/thread as TWO coalesced float4
//      streams (tt0, tt0+1024), CPB=16 rows/block => 1024 blocks = one full
//      wave. out[c,tt] = A[c,k[tt]] * w[tt], broadcast A reads, evict-first
//      float4 stores.
// ============================================================================

#define MAX_K 1024
#define MAX_T (1 << 18)
#define CPB   16

__device__ float d_w[MAX_T];
__device__ int   d_k[MAX_T];

// ---------------------------------------------------------------------------
// Expand kernel with fused block-parallel plan (round-6, unchanged).
// ---------------------------------------------------------------------------
__global__ void __launch_bounds__(256) expand_kernel(
    const float* __restrict__ L, int K, int T, float Tf)
{
    __shared__ float s_Lp[MAX_K];
    __shared__ int   s_cum[MAX_K + 1];
    __shared__ float sred[32];
    __shared__ int   sscan[32];
    __shared__ int   s_total;
    __shared__ float s_lmax;

    const int t    = threadIdx.x;
    const int lane = t & 31;
    const int warp = t >> 5;
    const int nw   = blockDim.x >> 5;                     // 8
    const int EPT  = (K + blockDim.x - 1) / blockDim.x;   // 1 for K=256
    const int base = t * EPT;

    float lv[4];
#pragma unroll
    for (int i = 0; i < 4; i++) {
        int k = base + i;
        lv[i] = (i < EPT && k < K) ? __ldg(L + k) : -INFINITY;
    }

    // block max(L)
    float mx = fmaxf(fmaxf(lv[0], lv[1]), fmaxf(lv[2], lv[3]));
    for (int o = 16; o; o >>= 1) mx = fmaxf(mx, __shfl_xor_sync(0xffffffffu, mx, o));
    if (lane == 0) sred[warp] = mx;
    __syncthreads();
    if (warp == 0) {
        float v = (lane < nw) ? sred[lane] : -INFINITY;
        for (int o = 16; o; o >>= 1) v = fmaxf(v, __shfl_xor_sync(0xffffffffu, v, o));
        if (lane == 0) sred[0] = v;
    }
    __syncthreads();
    mx = sred[0];
    __syncthreads();

    // block sum(exp)
    float e[4];
    float s = 0.0f;
#pragma unroll
    for (int i = 0; i < 4; i++) {
        int k = base + i;
        e[i] = (i < EPT && k < K) ? expf(lv[i] - mx) : 0.0f;
        s += e[i];
    }
    for (int o = 16; o; o >>= 1) s += __shfl_xor_sync(0xffffffffu, s, o);
    if (lane == 0) sred[warp] = s;
    __syncthreads();
    if (warp == 0) {
        float v = (lane < nw) ? sred[lane] : 0.0f;
        for (int o = 16; o; o >>= 1) v += __shfl_xor_sync(0xffffffffu, v, o);
        if (lane == 0) sred[0] = v;
    }
    __syncthreads();
    const float sum = sred[0];
    __syncthreads();

    // Lp -> smem, r = max(rint(Lp),0), maxLp
    float maxLp = -INFINITY;
    int rr[4];
    int rs = 0;
#pragma unroll
    for (int i = 0; i < 4; i++) {
        int k = base + i;
        if (i < EPT && k < K) {
            float Lp = Tf * __fdiv_rn(e[i], sum);
            s_Lp[k] = Lp;
            maxLp = fmaxf(maxLp, Lp);
            int r = (int)rintf(Lp);        // half-to-even == np.rint
            if (r < 0) r = 0;
            rr[i] = r;
            rs += r;
        } else rr[i] = 0;
    }

    // block max(Lp)
    float mLp = maxLp;
    for (int o = 16; o; o >>= 1) mLp = fmaxf(mLp, __shfl_xor_sync(0xffffffffu, mLp, o));
    if (lane == 0) sred[warp] = mLp;
    __syncthreads();
    if (warp == 0) {
        float v = (lane < nw) ? sred[lane] : -INFINITY;
        for (int o = 16; o; o >>= 1) v = fmaxf(v, __shfl_xor_sync(0xffffffffu, v, o));
        if (lane == 0) sred[0] = v;
    }

    // block scan of rs (two-level shfl)
    int incl = rs;
    for (int o = 1; o < 32; o <<= 1) {
        int v = __shfl_up_sync(0xffffffffu, incl, o);
        if (lane >= o) incl += v;
    }
    if (lane == 31) sscan[warp] = incl;
    __syncthreads();
    if (warp == 0) {
        int v = (lane < nw) ? sscan[lane] : 0;
        for (int o = 1; o < 32; o <<= 1) {
            int u = __shfl_up_sync(0xffffffffu, v, o);
            if (lane >= o) v += u;
        }
        if (lane < nw) sscan[lane] = v;    // inclusive warp totals
    }
    __syncthreads();

    const int warp_excl = (warp == 0) ? 0 : sscan[warp - 1];
    int running = warp_excl + (incl - rs);
#pragma unroll
    for (int i = 0; i < 4; i++) {
        int k = base + i;
        if (i < EPT && k < K) {
            running += rr[i];
            s_cum[k + 1] = running;
        }
    }
    if (t == 0) {
        s_cum[0] = 0;
        s_total  = sscan[nw - 1];
        double dm = (double)sred[0] + 0.5;
        s_lmax = (float)(long long)dm;     // int(max+0.5), trunc==floor (>=0)
    }
    __syncthreads();

    // expansion (4 columns / thread)
    const int tt0 = (blockIdx.x * blockDim.x + threadIdx.x) * 4;
    if (tt0 >= T) return;

    const int   total = s_total;
    const float lmaxf = s_lmax;

    const bool  pow2  = (T & (T - 1)) == 0;
    const int   shift = __ffs(T) - 1;
    const double ratio = (double)total / (double)T;

    float wv[4];
    int   kv[4];

#pragma unroll
    for (int i = 0; i < 4; i++) {
        int tt = tt0 + i;
        if (tt > T - 1) tt = T - 1;

        long long slot;
        if (pow2) {
            slot = ((long long)tt * (long long)total) >> shift;  // exact
        } else {
            slot = (long long)floor((double)tt * ratio);
        }
        if (slot > (long long)(total - 1)) slot = total - 1;
        if (slot < 0) slot = 0;

        int lo = 0, hi = K;
        const int si = (int)slot;
        while (hi - lo > 1) {
            int mid = (lo + hi) >> 1;
            if (s_cum[mid] <= si) lo = mid; else hi = mid;
        }
        const int k = lo;
        const int j = si - s_cum[k];

        const float Lp = s_Lp[k];
        const float x  = __fadd_rn(__fdiv_rn(__fadd_rn(__fmul_rn(2.0f, (float)j), 1.0f), lmaxf), -1.0f);
        const float sc = __fdiv_rn(lmaxf, Lp);
        const float tl = __fdiv_rn(__fadd_rn(lmaxf, -Lp), Lp);
        const float xs = __fadd_rn(__fmul_rn(sc, x), tl);
        const float p  = __fmul_rn(__fadd_rn(__fmul_rn(__fadd_rn(xs, 1.0f), 100.0f), -1.0f), 0.5f);
        const float p0 = floorf(p);
        const float w1 = __fadd_rn(p, -p0);
        const float in0 = (p0 >=  0.0f && p0 <= 99.0f) ? 1.0f : 0.0f;
        const float in1 = (p0 >= -1.0f && p0 <= 98.0f) ? 1.0f : 0.0f;
        wv[i] = __fadd_rn(__fmul_rn(__fadd_rn(1.0f, -w1), in0), __fmul_rn(w1, in1));
        kv[i] = k;
    }

    if (tt0 + 3 < T) {
        *reinterpret_cast<float4*>(&d_w[tt0]) = make_float4(wv[0], wv[1], wv[2], wv[3]);
        *reinterpret_cast<int4*>  (&d_k[tt0]) = make_int4(kv[0], kv[1], kv[2], kv[3]);
    } else {
        for (int i = 0; i < 4 && tt0 + i < T; i++) {
            d_w[tt0 + i] = wv[i];
            d_k[tt0 + i] = kv[i];
        }
    }
}

// ---------------------------------------------------------------------------
// Fill kernel (hot). 8 cols/thread = two coalesced float4 streams at
// tt0 and tt0+1024. CPB=16 rows/block.
// ---------------------------------------------------------------------------
__global__ void __launch_bounds__(256) fill_kernel(
    const float* __restrict__ A,
    float* __restrict__ out,
    int K, int T, int C)
{
    const int base = blockIdx.x * (256 * 8);
    const int tt0  = base + threadIdx.x * 4;
    const int tt1  = tt0 + 1024;
    if (tt0 >= T) return;

    const bool vec0 = (tt0 + 3 < T);
    const bool vec1 = (tt1 + 3 < T);

    float4 w0, w1v;
    int4   k0, k1v;

    if (vec0) {
        w0 = *reinterpret_cast<const float4*>(&d_w[tt0]);
        k0 = *reinterpret_cast<const int4*>  (&d_k[tt0]);
    } else {
        w0 = make_float4(d_w[tt0], 0.f, 0.f, 0.f);
        k0 = make_int4(d_k[tt0], 0, 0, 0);
        if (tt0 + 1 < T) { w0.y = d_w[tt0 + 1]; k0.y = d_k[tt0 + 1]; }
        if (tt0 + 2 < T) { w0.z = d_w[tt0 + 2]; k0.z = d_k[tt0 + 2]; }
    }
    if (vec1) {
        w1v = *reinterpret_cast<const float4*>(&d_w[tt1]);
        k1v = *reinterpret_cast<const int4*>  (&d_k[tt1]);
    } else {
        w1v = make_float4(0.f, 0.f, 0.f, 0.f);
        k1v = make_int4(0, 0, 0, 0);
        if (tt1     < T) { w1v.x = d_w[tt1];     k1v.x = d_k[tt1]; }
        if (tt1 + 1 < T) { w1v.y = d_w[tt1 + 1]; k1v.y = d_k[tt1 + 1]; }
        if (tt1 + 2 < T) { w1v.z = d_w[tt1 + 2]; k1v.z = d_k[tt1 + 2]; }
    }

    const int c0 = blockIdx.y * CPB;
    int c1 = c0 + CPB;
    if (c1 > C) c1 = C;

    // k monotone: ends equal => whole float4 uniform.
    const bool same0 = (k0.x == k0.w);
    const bool same1 = (k1v.x == k1v.w);

    if (same0 & same1 & vec0 & vec1) {
        // fast path: one broadcast A-load per stream per c, two indep stores
        const float* Ap0 = A + (size_t)c0 * (size_t)K + k0.x;
        const float* Ap1 = A + (size_t)c0 * (size_t)K + k1v.x;
        float* op0 = out + (size_t)c0 * (size_t)T + tt0;
        float* op1 = out + (size_t)c0 * (size_t)T + tt1;
#pragma unroll 4
        for (int c = c0; c < c1; ++c) {
            const float a0 = __ldg(Ap0);
            const float a1 = __ldg(Ap1);
            __stcs(reinterpret_cast<float4*>(op0),
                   make_float4(a0 * w0.x, a0 * w0.y, a0 * w0.z, a0 * w0.w));
            __stcs(reinterpret_cast<float4*>(op1),
                   make_float4(a1 * w1v.x, a1 * w1v.y, a1 * w1v.z, a1 * w1v.w));
            Ap0 += K; Ap1 += K;
            op0 += T; op1 += T;
        }
    } else {
        // general path (k transition inside a float4, or tail): rare
        for (int c = c0; c < c1; ++c) {
            const float* Ar = A + (size_t)c * (size_t)K;
            float* orow = out + (size_t)c * (size_t)T;

            float4 o0;
            o0.x = __ldg(Ar + k0.x) * w0.x;
            o0.y = __ldg(Ar + k0.y) * w0.y;
            o0.z = __ldg(Ar + k0.z) * w0.z;
            o0.w = __ldg(Ar + k0.w) * w0.w;
            if (vec0) {
                __stcs(reinterpret_cast<float4*>(orow + tt0), o0);
            } else {
                if (tt0     < T) orow[tt0]     = o0.x;
                if (tt0 + 1 < T) orow[tt0 + 1] = o0.y;
                if (tt0 + 2 < T) orow[tt0 + 2] = o0.z;
                if (tt0 + 3 < T) orow[tt0 + 3] = o0.w;
            }

            if (tt1 < T) {
                float4 o1;
                o1.x = __ldg(Ar + k1v.x) * w1v.x;
                o1.y = __ldg(Ar + k1v.y) * w1v.y;
                o1.z = __ldg(Ar + k1v.z) * w1v.z;
                o1.w = __ldg(Ar + k1v.w) * w1v.w;
                if (vec1) {
                    __stcs(reinterpret_cast<float4*>(orow + tt1), o1);
                } else {
                    if (tt1     < T) orow[tt1]     = o1.x;
                    if (tt1 + 1 < T) orow[tt1 + 1] = o1.y;
                    if (tt1 + 2 < T) orow[tt1 + 2] = o1.z;
                    if (tt1 + 3 < T) orow[tt1 + 3] = o1.w;
                }
            }
        }
    }
}

// ---------------------------------------------------------------------------
extern "C" void kernel_launch(void* const* d_in, const int* in_sizes, int n_in,
                              void* d_out, int out_size)
{
    const float* A = (const float*)d_in[0];   // [C, K]
    const float* L = (const float*)d_in[1];   // [K]

    const int K = in_sizes[1];
    const int C = in_sizes[0] / K;
    const int T = out_size / C;               // out is [1, C, T]

    // expand: 128 blocks x 1024 cols
    const int ex_cols = 256 * 4;
    const int ex_gx   = (T + ex_cols - 1) / ex_cols;
    expand_kernel<<<ex_gx, 256>>>(L, K, T, (float)T);

    // fill: 2048 cols/block, CPB rows/block
    const int fi_cols = 256 * 8;
    const int fi_gx   = (T + fi_cols - 1) / fi_cols;
    dim3 grid(fi_gx, (C + CPB - 1) / CPB);
    fill_kernel<<<grid, 256>>>(A, (float*)d_out, K, T, C);
}

// round 10
// speedup vs baseline: 1.3947x; 1.1236x over previous
#include <cuda_runtime.h>
#include <math.h>
#include <stdint.h>

// ============================================================================
// TemporalSamplingUpSampler — 2-phase (round-6 structure):
//   1) expand_kernel<<<128,256>>>: per-block fused plan (softmax, rint,
//      prefix-sum, lmax) + column expansion -> d_w[T], d_k[T].
//   2) fill kernel: out[c,tt] = A[c,k[tt]] * w[tt]. Round-6 thread shape
//      (4 cols/thread, broadcast A fast path, float4 evict-first stores),
//      CPB=16 c-rows/block, plus a tail-free specialization for aligned
//      shapes (T % 1024 == 0, C % CPB == 0) to cut registers.
// ============================================================================

#define MAX_K 1024
#define MAX_T (1 << 18)
#define CPB   16

__device__ float d_w[MAX_T];
__device__ int   d_k[MAX_T];

// ---------------------------------------------------------------------------
// Expand kernel with fused block-parallel plan (round-6, unchanged).
// ---------------------------------------------------------------------------
__global__ void __launch_bounds__(256) expand_kernel(
    const float* __restrict__ L, int K, int T, float Tf)
{
    __shared__ float s_Lp[MAX_K];
    __shared__ int   s_cum[MAX_K + 1];
    __shared__ float sred[32];
    __shared__ int   sscan[32];
    __shared__ int   s_total;
    __shared__ float s_lmax;

    const int t    = threadIdx.x;
    const int lane = t & 31;
    const int warp = t >> 5;
    const int nw   = blockDim.x >> 5;                     // 8
    const int EPT  = (K + blockDim.x - 1) / blockDim.x;   // 1 for K=256
    const int base = t * EPT;

    float lv[4];
#pragma unroll
    for (int i = 0; i < 4; i++) {
        int k = base + i;
        lv[i] = (i < EPT && k < K) ? __ldg(L + k) : -INFINITY;
    }

    // block max(L)
    float mx = fmaxf(fmaxf(lv[0], lv[1]), fmaxf(lv[2], lv[3]));
    for (int o = 16; o; o >>= 1) mx = fmaxf(mx, __shfl_xor_sync(0xffffffffu, mx, o));
    if (lane == 0) sred[warp] = mx;
    __syncthreads();
    if (warp == 0) {
        float v = (lane < nw) ? sred[lane] : -INFINITY;
        for (int o = 16; o; o >>= 1) v = fmaxf(v, __shfl_xor_sync(0xffffffffu, v, o));
        if (lane == 0) sred[0] = v;
    }
    __syncthreads();
    mx = sred[0];
    __syncthreads();

    // block sum(exp)
    float e[4];
    float s = 0.0f;
#pragma unroll
    for (int i = 0; i < 4; i++) {
        int k = base + i;
        e[i] = (i < EPT && k < K) ? expf(lv[i] - mx) : 0.0f;
        s += e[i];
    }
    for (int o = 16; o; o >>= 1) s += __shfl_xor_sync(0xffffffffu, s, o);
    if (lane == 0) sred[warp] = s;
    __syncthreads();
    if (warp == 0) {
        float v = (lane < nw) ? sred[lane] : 0.0f;
        for (int o = 16; o; o >>= 1) v += __shfl_xor_sync(0xffffffffu, v, o);
        if (lane == 0) sred[0] = v;
    }
    __syncthreads();
    const float sum = sred[0];
    __syncthreads();

    // Lp -> smem, r = max(rint(Lp),0), maxLp
    float maxLp = -INFINITY;
    int rr[4];
    int rs = 0;
#pragma unroll
    for (int i = 0; i < 4; i++) {
        int k = base + i;
        if (i < EPT && k < K) {
            float Lp = Tf * __fdiv_rn(e[i], sum);
            s_Lp[k] = Lp;
            maxLp = fmaxf(maxLp, Lp);
            int r = (int)rintf(Lp);        // half-to-even == np.rint
            if (r < 0) r = 0;
            rr[i] = r;
            rs += r;
        } else rr[i] = 0;
    }

    // block max(Lp)
    float mLp = maxLp;
    for (int o = 16; o; o >>= 1) mLp = fmaxf(mLp, __shfl_xor_sync(0xffffffffu, mLp, o));
    if (lane == 0) sred[warp] = mLp;
    __syncthreads();
    if (warp == 0) {
        float v = (lane < nw) ? sred[lane] : -INFINITY;
        for (int o = 16; o; o >>= 1) v = fmaxf(v, __shfl_xor_sync(0xffffffffu, v, o));
        if (lane == 0) sred[0] = v;
    }

    // block scan of rs (two-level shfl)
    int incl = rs;
    for (int o = 1; o < 32; o <<= 1) {
        int v = __shfl_up_sync(0xffffffffu, incl, o);
        if (lane >= o) incl += v;
    }
    if (lane == 31) sscan[warp] = incl;
    __syncthreads();
    if (warp == 0) {
        int v = (lane < nw) ? sscan[lane] : 0;
        for (int o = 1; o < 32; o <<= 1) {
            int u = __shfl_up_sync(0xffffffffu, v, o);
            if (lane >= o) v += u;
        }
        if (lane < nw) sscan[lane] = v;    // inclusive warp totals
    }
    __syncthreads();

    const int warp_excl = (warp == 0) ? 0 : sscan[warp - 1];
    int running = warp_excl + (incl - rs);
#pragma unroll
    for (int i = 0; i < 4; i++) {
        int k = base + i;
        if (i < EPT && k < K) {
            running += rr[i];
            s_cum[k + 1] = running;
        }
    }
    if (t == 0) {
        s_cum[0] = 0;
        s_total  = sscan[nw - 1];
        double dm = (double)sred[0] + 0.5;
        s_lmax = (float)(long long)dm;     // int(max+0.5), trunc==floor (>=0)
    }
    __syncthreads();

    // expansion (4 columns / thread)
    const int tt0 = (blockIdx.x * blockDim.x + threadIdx.x) * 4;
    if (tt0 >= T) return;

    const int   total = s_total;
    const float lmaxf = s_lmax;

    const bool  pow2  = (T & (T - 1)) == 0;
    const int   shift = __ffs(T) - 1;
    const double ratio = (double)total / (double)T;

    float wv[4];
    int   kv[4];

#pragma unroll
    for (int i = 0; i < 4; i++) {
        int tt = tt0 + i;
        if (tt > T - 1) tt = T - 1;

        long long slot;
        if (pow2) {
            slot = ((long long)tt * (long long)total) >> shift;  // exact
        } else {
            slot = (long long)floor((double)tt * ratio);
        }
        if (slot > (long long)(total - 1)) slot = total - 1;
        if (slot < 0) slot = 0;

        int lo = 0, hi = K;
        const int si = (int)slot;
        while (hi - lo > 1) {
            int mid = (lo + hi) >> 1;
            if (s_cum[mid] <= si) lo = mid; else hi = mid;
        }
        const int k = lo;
        const int j = si - s_cum[k];

        const float Lp = s_Lp[k];
        const float x  = __fadd_rn(__fdiv_rn(__fadd_rn(__fmul_rn(2.0f, (float)j), 1.0f), lmaxf), -1.0f);
        const float sc = __fdiv_rn(lmaxf, Lp);
        const float tl = __fdiv_rn(__fadd_rn(lmaxf, -Lp), Lp);
        const float xs = __fadd_rn(__fmul_rn(sc, x), tl);
        const float p  = __fmul_rn(__fadd_rn(__fmul_rn(__fadd_rn(xs, 1.0f), 100.0f), -1.0f), 0.5f);
        const float p0 = floorf(p);
        const float w1 = __fadd_rn(p, -p0);
        const float in0 = (p0 >=  0.0f && p0 <= 99.0f) ? 1.0f : 0.0f;
        const float in1 = (p0 >= -1.0f && p0 <= 98.0f) ? 1.0f : 0.0f;
        wv[i] = __fadd_rn(__fmul_rn(__fadd_rn(1.0f, -w1), in0), __fmul_rn(w1, in1));
        kv[i] = k;
    }

    if (tt0 + 3 < T) {
        *reinterpret_cast<float4*>(&d_w[tt0]) = make_float4(wv[0], wv[1], wv[2], wv[3]);
        *reinterpret_cast<int4*>  (&d_k[tt0]) = make_int4(kv[0], kv[1], kv[2], kv[3]);
    } else {
        for (int i = 0; i < 4 && tt0 + i < T; i++) {
            d_w[tt0 + i] = wv[i];
            d_k[tt0 + i] = kv[i];
        }
    }
}

// ---------------------------------------------------------------------------
// Fill kernel, ALIGNED specialization: requires T % (256*4) == 0 and
// C % CPB == 0. No tail guards anywhere -> minimal registers.
// ---------------------------------------------------------------------------
__global__ void __launch_bounds__(256) fill_aligned_kernel(
    const float* __restrict__ A,
    float* __restrict__ out,
    int K, int T)
{
    const int tt0 = (blockIdx.x * blockDim.x + threadIdx.x) * 4;

    const float4 w = *reinterpret_cast<const float4*>(&d_w[tt0]);
    const int4   k = *reinterpret_cast<const int4*>  (&d_k[tt0]);

    const int c0 = blockIdx.y * CPB;

    if (k.x == k.w) {
        // broadcast fast path: one A load per c
        const float* Ap = A + (size_t)c0 * (size_t)K + k.x;
        float* op = out + (size_t)c0 * (size_t)T + tt0;
#pragma unroll 4
        for (int i = 0; i < CPB; ++i) {
            const float a = __ldg(Ap);
            __stcs(reinterpret_cast<float4*>(op),
                   make_float4(a * w.x, a * w.y, a * w.z, a * w.w));
            Ap += K;
            op += T;
        }
    } else {
        const float* Ar = A + (size_t)c0 * (size_t)K;
        float* op = out + (size_t)c0 * (size_t)T + tt0;
#pragma unroll 4
        for (int i = 0; i < CPB; ++i) {
            float4 o;
            o.x = __ldg(Ar + k.x) * w.x;
            o.y = __ldg(Ar + k.y) * w.y;
            o.z = __ldg(Ar + k.z) * w.z;
            o.w = __ldg(Ar + k.w) * w.w;
            __stcs(reinterpret_cast<float4*>(op), o);
            Ar += K;
            op += T;
        }
    }
}

// ---------------------------------------------------------------------------
// Fill kernel, generic fallback (round-6 body, c_per_block runtime).
// ---------------------------------------------------------------------------
__global__ void __launch_bounds__(256) fill_kernel(
    const float* __restrict__ A,
    float* __restrict__ out,
    int K, int T, int C, int c_per_block)
{
    const int tt0 = (blockIdx.x * blockDim.x + threadIdx.x) * 4;
    if (tt0 >= T) return;

    const bool vec = (tt0 + 3 < T);

    float4 w;
    int4   k;
    if (vec) {
        w = *reinterpret_cast<const float4*>(&d_w[tt0]);
        k = *reinterpret_cast<const int4*>  (&d_k[tt0]);
    } else {
        w = make_float4(d_w[tt0], 0.f, 0.f, 0.f);
        k = make_int4(d_k[tt0], 0, 0, 0);
        if (tt0 + 1 < T) { w.y = d_w[tt0 + 1]; k.y = d_k[tt0 + 1]; }
        if (tt0 + 2 < T) { w.z = d_w[tt0 + 2]; k.z = d_k[tt0 + 2]; }
    }

    const int c0 = blockIdx.y * c_per_block;
    int c1 = c0 + c_per_block;
    if (c1 > C) c1 = C;

    const bool same = (k.x == k.w);

    if (same & vec) {
        const float* Ap = A + (size_t)c0 * (size_t)K + k.x;
        float* op = out + (size_t)c0 * (size_t)T + tt0;
#pragma unroll 4
        for (int c = c0; c < c1; ++c) {
            const float a = __ldg(Ap);
            float4 o = make_float4(a * w.x, a * w.y, a * w.z, a * w.w);
            __stcs(reinterpret_cast<float4*>(op), o);
            Ap += K;
            op += T;
        }
    } else {
        for (int c = c0; c < c1; ++c) {
            const float* Ar = A + (size_t)c * (size_t)K;
            float4 o;
            o.x = __ldg(Ar + k.x) * w.x;
            o.y = __ldg(Ar + k.y) * w.y;
            o.z = __ldg(Ar + k.z) * w.z;
            o.w = __ldg(Ar + k.w) * w.w;
            float* op = out + (size_t)c * (size_t)T + tt0;
            if (vec) {
                __stcs(reinterpret_cast<float4*>(op), o);
            } else {
                if (tt0     < T) op[0] = o.x;
                if (tt0 + 1 < T) op[1] = o.y;
                if (tt0 + 2 < T) op[2] = o.z;
                if (tt0 + 3 < T) op[3] = o.w;
            }
        }
    }
}

// ---------------------------------------------------------------------------
extern "C" void kernel_launch(void* const* d_in, const int* in_sizes, int n_in,
                              void* d_out, int out_size)
{
    const float* A = (const float*)d_in[0];   // [C, K]
    const float* L = (const float*)d_in[1];   // [K]

    const int K = in_sizes[1];
    const int C = in_sizes[0] / K;
    const int T = out_size / C;               // out is [1, C, T]

    // expand: 1024 cols per block
    const int ex_cols = 256 * 4;
    const int ex_gx   = (T + ex_cols - 1) / ex_cols;
    expand_kernel<<<ex_gx, 256>>>(L, K, T, (float)T);

    const int cols_per_block = 256 * 4;
    const int gx = (T + cols_per_block - 1) / cols_per_block;

    if ((T % cols_per_block == 0) && (C % CPB == 0)) {
        dim3 grid(gx, C / CPB);
        fill_aligned_kernel<<<grid, 256>>>(A, (float*)d_out, K, T);
    } else {
        dim3 grid(gx, (C + CPB - 1) / CPB);
        fill_kernel<<<grid, 256>>>(A, (float*)d_out, K, T, C, CPB);
    }
}